// round 1
// baseline (speedup 1.0000x reference)
#include <cuda_runtime.h>
#include <cuda_bf16.h>
#include <math.h>

// Problem constants (fixed shapes from reference)
#define V_   4
#define T_   4
#define NS_  100000
#define NH_  12288
#define E_   100000
#define H_   64
#define ET_  (V_ * T_)          // 16 edge types (v, t')
#define NEG_SLOPE 0.01f

// ---------------- scratch (static __device__, no allocation) ----------------
__device__ int   g_deg_out[ET_ * NS_];          // 1,600,000 ints  (6.4 MB)
__device__ int   g_deg_in [ET_ * NH_];          //   196,608 ints  (0.79 MB)
__device__ float g_s      [ET_ * T_ * NH_];     //   786,432 floats (3 MB)  layout: ((v*T+tp)*T + t)*NH + n

// ---------------- kernel 1: zero all scratch ----------------
__global__ void k_zero() {
    const int total = ET_ * NS_ + ET_ * NH_ + ET_ * T_ * NH_;
    for (int i = blockIdx.x * blockDim.x + threadIdx.x; i < total;
         i += gridDim.x * blockDim.x) {
        if (i < ET_ * NS_) {
            g_deg_out[i] = 0;
        } else if (i < ET_ * NS_ + ET_ * NH_) {
            g_deg_in[i - ET_ * NS_] = 0;
        } else {
            g_s[i - ET_ * NS_ - ET_ * NH_] = 0.0f;
        }
    }
}

// ---------------- kernel 2: degree counts ----------------
__global__ void k_degrees(const int* __restrict__ src_idx,
                          const int* __restrict__ dst_idx) {
    int i = blockIdx.x * blockDim.x + threadIdx.x;   // over ET_*E_
    if (i >= ET_ * E_) return;
    int et = i / E_;
    int s  = src_idx[i];
    int d  = dst_idx[i];
    atomicAdd(&g_deg_out[et * NS_ + s], 1);
    atomicAdd(&g_deg_in [et * NH_ + d], 1);
}

// ---------------- kernel 3: normalized scatter ----------------
// s_raw[v,tp,t,n] += x[v,t,src] * rsqrt(max(deg_out[v,tp,src],1))  over edges of etype (v,tp)
__global__ void k_scatter(const float* __restrict__ x,
                          const int* __restrict__ src_idx,
                          const int* __restrict__ dst_idx) {
    int i = blockIdx.x * blockDim.x + threadIdx.x;   // over ET_*E_
    if (i >= ET_ * E_) return;
    int et = i / E_;                                  // et = v*T + tp
    int v  = et / T_;
    int s  = src_idx[i];
    int d  = dst_idx[i];
    float ns = rsqrtf(fmaxf((float)g_deg_out[et * NS_ + s], 1.0f));
#pragma unroll
    for (int t = 0; t < T_; t++) {
        float xv = x[(v * T_ + t) * NS_ + s];
        if (isnan(xv)) xv = 0.0f;                     // nan_to_num
        atomicAdd(&g_s[(et * T_ + t) * NH_ + d], xv * ns);
    }
}

// ---------------- kernel 4: dst-side normalization (in place) ----------------
__global__ void k_scale() {
    int i = blockIdx.x * blockDim.x + threadIdx.x;    // over ET_*T_*NH_
    if (i >= ET_ * T_ * NH_) return;
    int n  = i % NH_;
    int et = i / (T_ * NH_);
    g_s[i] *= rsqrtf(fmaxf((float)g_deg_in[et * NH_ + n], 1.0f));
}

// ---------------- kernel 5: epilogue ----------------
// out[n,v,t,h] = sum_tp lrelu( s[v,tp,t,n] * W[v,tp,h] + b[v,tp,h] )
// One thread per (n, v, t, q) where q indexes float4 within H (16 per row).
__global__ void k_epilogue(const float4* __restrict__ W4,
                           const float4* __restrict__ b4,
                           float4* __restrict__ out4) {
    int tid = blockIdx.x * blockDim.x + threadIdx.x;  // NH_*V_*T_*16 = 3,145,728
    if (tid >= NH_ * V_ * T_ * (H_ / 4)) return;
    int q = tid & 15;
    int t = (tid >> 4) & 3;
    int v = (tid >> 6) & 3;
    int n = tid >> 8;

    float4 acc = make_float4(0.f, 0.f, 0.f, 0.f);
#pragma unroll
    for (int tp = 0; tp < T_; tp++) {
        int et = v * T_ + tp;
        float sv = g_s[(et * T_ + t) * NH_ + n];       // uniform across q (L1 broadcast)
        float4 w = W4[et * (H_ / 4) + q];              // tiny, L1-resident
        float4 bb = b4[et * (H_ / 4) + q];
        float y0 = fmaf(sv, w.x, bb.x);
        float y1 = fmaf(sv, w.y, bb.y);
        float y2 = fmaf(sv, w.z, bb.z);
        float y3 = fmaf(sv, w.w, bb.w);
        // leaky_relu(y) = max(y, 0.01*y)  (valid since slope < 1)
        acc.x += fmaxf(y0, NEG_SLOPE * y0);
        acc.y += fmaxf(y1, NEG_SLOPE * y1);
        acc.z += fmaxf(y2, NEG_SLOPE * y2);
        acc.w += fmaxf(y3, NEG_SLOPE * y3);
    }
    out4[tid] = acc;   // ((n*V+v)*T+t)*(H/4) + q  == tid by construction
}

// ---------------- launch ----------------
extern "C" void kernel_launch(void* const* d_in, const int* in_sizes, int n_in,
                              void* d_out, int out_size) {
    const float* x   = (const float*)d_in[0];   // [V,T,NS]
    const float* W   = (const float*)d_in[1];   // [V,T,H]
    const float* b   = (const float*)d_in[2];   // [V,T,H]
    const int* src   = (const int*)d_in[3];     // [V,T,E]
    const int* dst   = (const int*)d_in[4];     // [V,T,E]
    // d_in[5] = n_healpix (scalar) — shapes are compile-time constants here.

    const int threads = 256;

    // 1. zero scratch
    {
        const int total = ET_ * NS_ + ET_ * NH_ + ET_ * T_ * NH_;
        k_zero<<<(total + threads - 1) / threads, threads>>>();
    }
    // 2. degrees
    {
        const int total = ET_ * E_;
        k_degrees<<<(total + threads - 1) / threads, threads>>>(src, dst);
    }
    // 3. scatter
    {
        const int total = ET_ * E_;
        k_scatter<<<(total + threads - 1) / threads, threads>>>(x, src, dst);
    }
    // 4. dst norm
    {
        const int total = ET_ * T_ * NH_;
        k_scale<<<(total + threads - 1) / threads, threads>>>();
    }
    // 5. epilogue
    {
        const int total = NH_ * V_ * T_ * (H_ / 4);
        k_epilogue<<<(total + threads - 1) / threads, threads>>>(
            (const float4*)W, (const float4*)b, (float4*)d_out);
    }
}

// round 2
// speedup vs baseline: 1.1274x; 1.1274x over previous
#include <cuda_runtime.h>
#include <cuda_bf16.h>
#include <math.h>

// Problem constants (fixed shapes from reference)
#define V_   4
#define T_   4
#define NS_  100000
#define NH_  12288
#define E_   100000
#define H_   64
#define ET_  (V_ * T_)          // 16 edge types (v, t')
#define NEG_SLOPE 0.01f

// ---------------- scratch (static __device__, no allocation) ----------------
__device__ int    g_deg_out[ET_ * NS_];        // 6.4 MB   counts per (et, s)
__device__ int    g_deg_in [ET_ * NH_];        // 0.79 MB  counts per (et, n)
__device__ float  g_s      [ET_ * NH_ * T_];   // 3 MB     layout: (et, n, t)  (t innermost, float4-aligned)
__device__ float4 g_xT     [V_ * NS_];         // 6.4 MB   xT[v][s] = {x[v,0,s],x[v,1,s],x[v,2,s],x[v,3,s]} nan-cleaned

// ---------------- kernel 1: init (zero scratch + transpose x) ----------------
__global__ void k_init(const float* __restrict__ x) {
    int i = blockIdx.x * blockDim.x + threadIdx.x;
    int stride = gridDim.x * blockDim.x;
    const int4 z4 = make_int4(0, 0, 0, 0);

    // zero deg_out (1.6M ints = 400k int4)
    for (int j = i; j < ET_ * NS_ / 4; j += stride)
        ((int4*)g_deg_out)[j] = z4;
    // zero deg_in (196,608 ints = 49,152 int4)
    for (int j = i; j < ET_ * NH_ / 4; j += stride)
        ((int4*)g_deg_in)[j] = z4;
    // zero g_s (786,432 floats = 196,608 float4)
    for (int j = i; j < ET_ * NH_ * T_ / 4; j += stride)
        ((int4*)g_s)[j] = z4;
    // transpose x: [V,T,NS] -> xT[v][s] float4 over t, with nan_to_num
    for (int j = i; j < V_ * NS_; j += stride) {
        int v = j / NS_;
        int s = j - v * NS_;
        float4 r;
        float a0 = x[(v * T_ + 0) * NS_ + s];
        float a1 = x[(v * T_ + 1) * NS_ + s];
        float a2 = x[(v * T_ + 2) * NS_ + s];
        float a3 = x[(v * T_ + 3) * NS_ + s];
        r.x = isnan(a0) ? 0.0f : a0;
        r.y = isnan(a1) ? 0.0f : a1;
        r.z = isnan(a2) ? 0.0f : a2;
        r.w = isnan(a3) ? 0.0f : a3;
        g_xT[j] = r;
    }
}

// ---------------- kernel 2: degree counts ----------------
__global__ void k_degrees(const int* __restrict__ src_idx,
                          const int* __restrict__ dst_idx) {
    int i = blockIdx.x * blockDim.x + threadIdx.x;   // over ET_*E_
    if (i >= ET_ * E_) return;
    int et = i / E_;
    atomicAdd(&g_deg_out[et * NS_ + src_idx[i]], 1);
    atomicAdd(&g_deg_in [et * NH_ + dst_idx[i]], 1);
}

// ---------------- kernel 3: normalized scatter (vector atomics) ----------------
// g_s[et, d, t] += xT[v][s].t * rsqrt(max(deg_out[et,s],1))
__global__ void k_scatter(const int* __restrict__ src_idx,
                          const int* __restrict__ dst_idx) {
    int i = blockIdx.x * blockDim.x + threadIdx.x;   // over ET_*E_
    if (i >= ET_ * E_) return;
    int et = i / E_;                                  // et = v*T + tp
    int v  = et >> 2;
    int s  = src_idx[i];
    int d  = dst_idx[i];
    float ns = rsqrtf(fmaxf((float)g_deg_out[et * NS_ + s], 1.0f));
    float4 xv = g_xT[v * NS_ + s];
    float m0 = xv.x * ns, m1 = xv.y * ns, m2 = xv.z * ns, m3 = xv.w * ns;
    float* p = &g_s[(et * NH_ + d) * T_];
#if __CUDA_ARCH__ >= 900
    asm volatile("red.global.add.v4.f32 [%0], {%1, %2, %3, %4};"
                 :: "l"(p), "f"(m0), "f"(m1), "f"(m2), "f"(m3) : "memory");
#else
    atomicAdd(p + 0, m0);
    atomicAdd(p + 1, m1);
    atomicAdd(p + 2, m2);
    atomicAdd(p + 3, m3);
#endif
}

// ---------------- kernel 4: epilogue ----------------
// out[n,v,t,h] = sum_tp lrelu( s[et,n,t]*ndst[et,n] * W[et,h] + b[et,h] )
// Thread layout: tid = ((n*V + v)*T + t)*16 + q, q = float4 index within H.
__global__ void k_epilogue(const float4* __restrict__ W4,
                           const float4* __restrict__ b4,
                           float4* __restrict__ out4) {
    int tid = blockIdx.x * blockDim.x + threadIdx.x;  // NH_*V_*T_*16 = 3,145,728
    if (tid >= NH_ * V_ * T_ * (H_ / 4)) return;
    int q = tid & 15;
    int t = (tid >> 4) & 3;
    int v = (tid >> 6) & 3;
    int n = tid >> 8;

    float4 acc = make_float4(0.f, 0.f, 0.f, 0.f);
#pragma unroll
    for (int tp = 0; tp < T_; tp++) {
        int et = v * T_ + tp;
        float nd = rsqrtf(fmaxf((float)g_deg_in[et * NH_ + n], 1.0f)); // uniform across warp
        float sv = g_s[(et * NH_ + n) * T_ + t] * nd;                  // uniform across q
        float4 w  = W4[et * (H_ / 4) + q];                             // tiny, L1-resident
        float4 bb = b4[et * (H_ / 4) + q];
        float y0 = fmaf(sv, w.x, bb.x);
        float y1 = fmaf(sv, w.y, bb.y);
        float y2 = fmaf(sv, w.z, bb.z);
        float y3 = fmaf(sv, w.w, bb.w);
        acc.x += fmaxf(y0, NEG_SLOPE * y0);   // leaky_relu (slope<1)
        acc.y += fmaxf(y1, NEG_SLOPE * y1);
        acc.z += fmaxf(y2, NEG_SLOPE * y2);
        acc.w += fmaxf(y3, NEG_SLOPE * y3);
    }
    out4[tid] = acc;   // ((n*V+v)*T+t)*(H/4) + q == tid
}

// ---------------- launch ----------------
extern "C" void kernel_launch(void* const* d_in, const int* in_sizes, int n_in,
                              void* d_out, int out_size) {
    const float* x = (const float*)d_in[0];   // [V,T,NS]
    const float* W = (const float*)d_in[1];   // [V,T,H]
    const float* b = (const float*)d_in[2];   // [V,T,H]
    const int* src = (const int*)d_in[3];     // [V,T,E]
    const int* dst = (const int*)d_in[4];     // [V,T,E]

    const int threads = 256;

    // 1. init: zero scratch + transpose x (grid sized for the largest loop: 400k)
    k_init<<<(ET_ * NS_ / 4 + threads - 1) / threads, threads>>>(x);

    // 2. degrees
    k_degrees<<<(ET_ * E_ + threads - 1) / threads, threads>>>(src, dst);

    // 3. scatter
    k_scatter<<<(ET_ * E_ + threads - 1) / threads, threads>>>(src, dst);

    // 4. epilogue
    k_epilogue<<<(NH_ * V_ * T_ * (H_ / 4) + threads - 1) / threads, threads>>>(
        (const float4*)W, (const float4*)b, (float4*)d_out);
}

// round 5
// speedup vs baseline: 1.7376x; 1.5412x over previous
#include <cuda_runtime.h>
#include <cuda_bf16.h>
#include <math.h>

#define V_   4
#define T_   4
#define NS_  100000
#define NH_  12288
#define E_   100000
#define H_   64
#define ET_  (V_ * T_)
#define NEG_SLOPE 0.01f

// ---------------- scratch (static __device__, no allocation) ----------------
__device__ int    g_deg_out[ET_ * NS_];        // counts per (et, s)
__device__ int    g_deg_in [ET_ * NH_];        // counts per (et, n)
__device__ float  g_s      [ET_ * NH_ * T_];   // layout: (et, n, t), t innermost (float4)
__device__ float4 g_xT     [V_ * NS_];         // xT[v][s] over t, nan-cleaned

// ---------------- kernel 1: init (zero scratch + transpose x) ----------------
__global__ void k_init(const float* __restrict__ x) {
    int i = blockIdx.x * blockDim.x + threadIdx.x;
    int stride = gridDim.x * blockDim.x;
    const int4 z4 = make_int4(0, 0, 0, 0);
    for (int j = i; j < ET_ * NS_ / 4; j += stride)
        ((int4*)g_deg_out)[j] = z4;
    for (int j = i; j < ET_ * NH_ / 4; j += stride)
        ((int4*)g_deg_in)[j] = z4;
    for (int j = i; j < ET_ * NH_ * T_ / 4; j += stride)
        ((int4*)g_s)[j] = z4;
    for (int j = i; j < V_ * NS_; j += stride) {
        int v = j / NS_;
        int s = j - v * NS_;
        float4 r;
        float a0 = x[(v * T_ + 0) * NS_ + s];
        float a1 = x[(v * T_ + 1) * NS_ + s];
        float a2 = x[(v * T_ + 2) * NS_ + s];
        float a3 = x[(v * T_ + 3) * NS_ + s];
        r.x = isnan(a0) ? 0.0f : a0;
        r.y = isnan(a1) ? 0.0f : a1;
        r.z = isnan(a2) ? 0.0f : a2;
        r.w = isnan(a3) ? 0.0f : a3;
        g_xT[j] = r;
    }
}

// ---------------- kernel 2: degree counts (4 edges/thread) ----------------
__global__ void k_degrees(const int4* __restrict__ src4,
                          const int4* __restrict__ dst4) {
    int i = blockIdx.x * blockDim.x + threadIdx.x;   // over ET_*E_/4
    if (i >= ET_ * E_ / 4) return;
    int et = (i * 4) / E_;                           // 4-aligned group never straddles etypes
    int4 s = src4[i];
    int4 d = dst4[i];
    int* po = &g_deg_out[et * NS_];
    int* pi = &g_deg_in [et * NH_];
    atomicAdd(po + s.x, 1); atomicAdd(po + s.y, 1);
    atomicAdd(po + s.z, 1); atomicAdd(po + s.w, 1);
    atomicAdd(pi + d.x, 1); atomicAdd(pi + d.y, 1);
    atomicAdd(pi + d.z, 1); atomicAdd(pi + d.w, 1);
}

// ---------------- kernel 3: normalized scatter (2 edges/thread) ----------------
__device__ __forceinline__ void scatter_one(int et, int v, int s, int d) {
    float ns = rsqrtf(fmaxf((float)g_deg_out[et * NS_ + s], 1.0f));
    float4 xv = g_xT[v * NS_ + s];
    float m0 = xv.x * ns, m1 = xv.y * ns, m2 = xv.z * ns, m3 = xv.w * ns;
    float* p = &g_s[(et * NH_ + d) * T_];
    asm volatile("red.global.add.v4.f32 [%0], {%1, %2, %3, %4};"
                 :: "l"(p), "f"(m0), "f"(m1), "f"(m2), "f"(m3) : "memory");
}

__global__ void k_scatter(const int2* __restrict__ src2,
                          const int2* __restrict__ dst2) {
    int i = blockIdx.x * blockDim.x + threadIdx.x;   // over ET_*E_/2
    if (i >= ET_ * E_ / 2) return;
    int et = (i * 2) / E_;                           // 2-aligned group never straddles etypes
    int v  = et >> 2;
    int2 s = src2[i];
    int2 d = dst2[i];
    scatter_one(et, v, s.x, d.x);
    scatter_one(et, v, s.y, d.y);
}

// ---------------- kernel 4: epilogue (W/b hoisted to registers) ----------------
// out[n,v,t,h] = sum_tp lrelu( s[et,n,t]*nd[et,n] * W[et,h] + b[et,h] ),  et=v*4+tp
// Block = 256 threads: q = tx&15, t = (tx>>4)&3, v = tx>>6. Loop over n.
#define NPB 8   // n values per block
__global__ void __launch_bounds__(256) k_epilogue(const float4* __restrict__ W4,
                                                  const float4* __restrict__ b4,
                                                  float4* __restrict__ out4) {
    int tx = threadIdx.x;
    int q = tx & 15;
    int t = (tx >> 4) & 3;
    int v = tx >> 6;

    // hoist W/b: 4 tp each
    float4 w[T_], bb[T_];
#pragma unroll
    for (int tp = 0; tp < T_; tp++) {
        int et = v * T_ + tp;
        w[tp]  = W4[et * (H_ / 4) + q];
        bb[tp] = b4[et * (H_ / 4) + q];
    }

    int n0 = blockIdx.x * NPB;
#pragma unroll
    for (int k = 0; k < NPB; k++) {
        int n = n0 + k;
        float4 acc = make_float4(0.f, 0.f, 0.f, 0.f);
#pragma unroll
        for (int tp = 0; tp < T_; tp++) {
            int et = v * T_ + tp;
            float nd = rsqrtf(fmaxf((float)__ldg(&g_deg_in[et * NH_ + n]), 1.0f));
            float sv = __ldg(&g_s[(et * NH_ + n) * T_ + t]) * nd;
            float y0 = fmaf(sv, w[tp].x, bb[tp].x);
            float y1 = fmaf(sv, w[tp].y, bb[tp].y);
            float y2 = fmaf(sv, w[tp].z, bb[tp].z);
            float y3 = fmaf(sv, w[tp].w, bb[tp].w);
            acc.x += fmaxf(y0, NEG_SLOPE * y0);
            acc.y += fmaxf(y1, NEG_SLOPE * y1);
            acc.z += fmaxf(y2, NEG_SLOPE * y2);
            acc.w += fmaxf(y3, NEG_SLOPE * y3);
        }
        out4[((n * V_ + v) * T_ + t) * (H_ / 4) + q] = acc;  // coalesced per warp
    }
}

// ---------------- launch ----------------
extern "C" void kernel_launch(void* const* d_in, const int* in_sizes, int n_in,
                              void* d_out, int out_size) {
    const float* x = (const float*)d_in[0];
    const float* W = (const float*)d_in[1];
    const float* b = (const float*)d_in[2];
    const int* src = (const int*)d_in[3];
    const int* dst = (const int*)d_in[4];

    const int threads = 256;

    k_init<<<(ET_ * NS_ / 4 + threads - 1) / threads, threads>>>(x);

    k_degrees<<<(ET_ * E_ / 4 + threads - 1) / threads, threads>>>(
        (const int4*)src, (const int4*)dst);

    k_scatter<<<(ET_ * E_ / 2 + threads - 1) / threads, threads>>>(
        (const int2*)src, (const int2*)dst);

    k_epilogue<<<NH_ / NPB, 256>>>(
        (const float4*)W, (const float4*)b, (float4*)d_out);
}

// round 8
// speedup vs baseline: 1.8646x; 1.0731x over previous
#include <cuda_runtime.h>
#include <cuda_bf16.h>
#include <math.h>

#define V_   4
#define T_   4
#define NS_  100000
#define NH_  12288
#define E_   100000
#define H_   64
#define ET_  (V_ * T_)
#define NEG_SLOPE 0.01f

// ---------------- scratch (static __device__, no allocation) ----------------
__device__ int    g_deg_out[ET_ * NS_];        // counts per (et, s)
__device__ int    g_deg_in [ET_ * NH_];        // counts per (et, n)
__device__ float  g_s      [ET_ * NH_ * T_];   // (et, n, t), t innermost (float4-aligned)
__device__ float4 g_xT     [V_ * NS_];         // xT[v][s] over t, nan-cleaned

// ---------------- kernel 1: init (zero scratch + transpose x) ----------------
__global__ void k_init(const float* __restrict__ x) {
    int i = blockIdx.x * blockDim.x + threadIdx.x;
    int stride = gridDim.x * blockDim.x;
    const int4 z4 = make_int4(0, 0, 0, 0);
    for (int j = i; j < ET_ * NS_ / 4; j += stride)
        ((int4*)g_deg_out)[j] = z4;
    for (int j = i; j < ET_ * NH_ / 4; j += stride)
        ((int4*)g_deg_in)[j] = z4;
    for (int j = i; j < ET_ * NH_ * T_ / 4; j += stride)
        ((int4*)g_s)[j] = z4;
    for (int j = i; j < V_ * NS_; j += stride) {
        int v = j / NS_;
        int s = j - v * NS_;
        float4 r;
        float a0 = x[(v * T_ + 0) * NS_ + s];
        float a1 = x[(v * T_ + 1) * NS_ + s];
        float a2 = x[(v * T_ + 2) * NS_ + s];
        float a3 = x[(v * T_ + 3) * NS_ + s];
        r.x = isnan(a0) ? 0.0f : a0;
        r.y = isnan(a1) ? 0.0f : a1;
        r.z = isnan(a2) ? 0.0f : a2;
        r.w = isnan(a3) ? 0.0f : a3;
        g_xT[j] = r;
    }
}

// ---------------- kernel 2: degree counts (4 edges/thread) ----------------
__global__ void k_degrees(const int4* __restrict__ src4,
                          const int4* __restrict__ dst4) {
    int i = blockIdx.x * blockDim.x + threadIdx.x;   // over ET_*E_/4
    if (i >= ET_ * E_ / 4) return;
    int et = (i * 4) / E_;                           // groups never straddle etypes
    int4 s = src4[i];
    int4 d = dst4[i];
    int* po = &g_deg_out[et * NS_];
    int* pi = &g_deg_in [et * NH_];
    atomicAdd(po + s.x, 1); atomicAdd(po + s.y, 1);
    atomicAdd(po + s.z, 1); atomicAdd(po + s.w, 1);
    atomicAdd(pi + d.x, 1); atomicAdd(pi + d.y, 1);
    atomicAdd(pi + d.z, 1); atomicAdd(pi + d.w, 1);
}

// ---------------- kernel 3: normalized scatter (4 edges/thread, batched MLP) ----------------
__device__ __forceinline__ void red_v4(float* p, float4 xv, float ns) {
    asm volatile("red.global.add.v4.f32 [%0], {%1, %2, %3, %4};"
                 :: "l"(p), "f"(xv.x * ns), "f"(xv.y * ns),
                    "f"(xv.z * ns), "f"(xv.w * ns) : "memory");
}

__global__ void k_scatter(const int4* __restrict__ src4,
                          const int4* __restrict__ dst4) {
    int i = blockIdx.x * blockDim.x + threadIdx.x;   // over ET_*E_/4
    if (i >= ET_ * E_ / 4) return;
    int et = (i * 4) / E_;                           // groups never straddle etypes
    int v  = et >> 2;
    int4 s = src4[i];
    int4 d = dst4[i];

    // batch all gathers first -> MLP 8 over ~240cy L2 latency
    int dg0 = __ldg(&g_deg_out[et * NS_ + s.x]);
    int dg1 = __ldg(&g_deg_out[et * NS_ + s.y]);
    int dg2 = __ldg(&g_deg_out[et * NS_ + s.z]);
    int dg3 = __ldg(&g_deg_out[et * NS_ + s.w]);
    float4 x0 = __ldg(&g_xT[v * NS_ + s.x]);
    float4 x1 = __ldg(&g_xT[v * NS_ + s.y]);
    float4 x2 = __ldg(&g_xT[v * NS_ + s.z]);
    float4 x3 = __ldg(&g_xT[v * NS_ + s.w]);

    float n0 = rsqrtf(fmaxf((float)dg0, 1.0f));
    float n1 = rsqrtf(fmaxf((float)dg1, 1.0f));
    float n2 = rsqrtf(fmaxf((float)dg2, 1.0f));
    float n3 = rsqrtf(fmaxf((float)dg3, 1.0f));

    float* base = &g_s[et * NH_ * T_];
    red_v4(base + d.x * T_, x0, n0);
    red_v4(base + d.y * T_, x1, n1);
    red_v4(base + d.z * T_, x2, n2);
    red_v4(base + d.w * T_, x3, n3);
}

// ---------------- kernel 4: epilogue (smem-staged s*nd, W/b in regs) ----------------
// out[n,v,t,h] = sum_tp lrelu( z[et,n,t] * W[et,h] + b[et,h] ),  z = s * rsqrt(deg_in)
#define NPB 8   // n values per block
__global__ void __launch_bounds__(256) k_epilogue(const float4* __restrict__ W4,
                                                  const float4* __restrict__ b4,
                                                  float4* __restrict__ out4) {
    __shared__ float4 zsm[ET_ * NPB];   // z[et][k] over t (float4)

    int tx = threadIdx.x;
    int n0 = blockIdx.x * NPB;

    // stage: 128 threads compute z = s * rsqrt(max(deg_in,1)) once per (et,k)
    if (tx < ET_ * NPB) {
        int et = tx >> 3;           // /NPB
        int k  = tx & (NPB - 1);
        int n  = n0 + k;
        float nd = rsqrtf(fmaxf((float)__ldg(&g_deg_in[et * NH_ + n]), 1.0f));
        float4 sv = *(const float4*)&g_s[(et * NH_ + n) * T_];
        sv.x *= nd; sv.y *= nd; sv.z *= nd; sv.w *= nd;
        zsm[tx] = sv;
    }

    int q = tx & 15;
    int t = (tx >> 4) & 3;
    int v = tx >> 6;

    // hoist W/b into registers (4 tp each)
    float4 w[T_], bb[T_];
#pragma unroll
    for (int tp = 0; tp < T_; tp++) {
        int et = v * T_ + tp;
        w[tp]  = W4[et * (H_ / 4) + q];
        bb[tp] = b4[et * (H_ / 4) + q];
    }

    __syncthreads();

#pragma unroll
    for (int k = 0; k < NPB; k++) {
        float4 acc = make_float4(0.f, 0.f, 0.f, 0.f);
#pragma unroll
        for (int tp = 0; tp < T_; tp++) {
            int et = v * T_ + tp;
            float sv = ((const float*)&zsm[et * NPB + k])[t];   // LDS broadcast
            float y0 = fmaf(sv, w[tp].x, bb[tp].x);
            float y1 = fmaf(sv, w[tp].y, bb[tp].y);
            float y2 = fmaf(sv, w[tp].z, bb[tp].z);
            float y3 = fmaf(sv, w[tp].w, bb[tp].w);
            acc.x += fmaxf(y0, NEG_SLOPE * y0);
            acc.y += fmaxf(y1, NEG_SLOPE * y1);
            acc.z += fmaxf(y2, NEG_SLOPE * y2);
            acc.w += fmaxf(y3, NEG_SLOPE * y3);
        }
        int n = n0 + k;
        out4[((n * V_ + v) * T_ + t) * (H_ / 4) + q] = acc;     // coalesced
    }
}

// ---------------- launch ----------------
extern "C" void kernel_launch(void* const* d_in, const int* in_sizes, int n_in,
                              void* d_out, int out_size) {
    const float* x = (const float*)d_in[0];
    const float* W = (const float*)d_in[1];
    const float* b = (const float*)d_in[2];
    const int* src = (const int*)d_in[3];
    const int* dst = (const int*)d_in[4];

    const int threads = 256;

    k_init<<<(ET_ * NS_ / 4 + threads - 1) / threads, threads>>>(x);

    k_degrees<<<(ET_ * E_ / 4 + threads - 1) / threads, threads>>>(
        (const int4*)src, (const int4*)dst);

    k_scatter<<<(ET_ * E_ / 4 + threads - 1) / threads, threads>>>(
        (const int4*)src, (const int4*)dst);

    k_epilogue<<<NH_ / NPB, 256>>>(
        (const float4*)W, (const float4*)b, (float4*)d_out);
}